// round 5
// baseline (speedup 1.0000x reference)
#include <cuda_runtime.h>

#define NB     4
#define IN_DIM 8
#define OUT_D  64
#define N_WIN  64
#define N_SEQ  4096
#define N_REAL 6144
#define PAD    64
#define ROW    (PAD + N_REAL + 8)   // 6216 floats per (b,i) row, front pad for t-w<0, tail pad for shifted load
#define TT     128                  // t per block
#define OB     16                   // o per block
#define XLEN   192                  // TT + N_WIN
#define XDIM   200                  // padded shared row

__device__ __align__(16) float g_X[NB][IN_DIM][ROW];

// ---------------- zero + scatter ----------------

__global__ void zero_kernel() {
    int t = blockIdx.x * blockDim.x + threadIdx.x;
    const int total = NB * IN_DIM * ROW / 4;
    if (t < total)
        reinterpret_cast<float4*>(g_X)[t] = make_float4(0.f, 0.f, 0.f, 0.f);
}

__global__ void scatter_kernel(const float* __restrict__ x, const int* __restrict__ idx) {
    int t = blockIdx.x * blockDim.x + threadIdx.x;
    if (t >= NB * IN_DIM * N_SEQ) return;
    int s  = t & (N_SEQ - 1);
    int bi = t >> 12;            // N_SEQ = 4096
    int i  = bi & (IN_DIM - 1);
    int b  = bi >> 3;
    int p  = idx[b * N_SEQ + s];
    g_X[b][i][PAD + p] = x[t];
}

// ---------------- f32x2 helpers ----------------

__device__ __forceinline__ unsigned long long ffma2(unsigned long long a,
                                                    unsigned long long b,
                                                    unsigned long long c) {
    unsigned long long d;
    asm("fma.rn.f32x2 %0, %1, %2, %3;" : "=l"(d) : "l"(a), "l"(b), "l"(c));
    return d;
}
__device__ __forceinline__ unsigned long long pack2(float v) {
    unsigned long long r;
    unsigned int u = __float_as_uint(v);
    asm("mov.b64 %0, {%1, %1};" : "=l"(r) : "r"(u));
    return r;
}
__device__ __forceinline__ float2 unpack2(unsigned long long v) {
    float2 r;
    asm("mov.b64 {%0, %1}, %2;" : "=f"(r.x), "=f"(r.y) : "l"(v));
    return r;
}
__device__ __forceinline__ unsigned long long lds2(const float* p) {
    return *reinterpret_cast<const unsigned long long*>(p);
}

// ---------------- conv: out[b,o,t] = bias[o] + sum_{i,w} W[o,i,w] * Xhat[b,i,t-w] ----------------
// Block: one b, OB=16 o-rows, TT=128 t-values. 4 warps; warp handles 4 o-rows;
// lane handles t-pairs {2*lane, 2*lane+1} and {2*lane+64, 2*lane+65}.
// sXa[j] = Xhat[T0-64+j] (aligned pairs for even w); sXb[j] = sXa[j+1] (aligned pairs for odd w).

__global__ __launch_bounds__(128, 4)
void conv_kernel(const float* __restrict__ weight,
                 const float* __restrict__ bias,
                 float* __restrict__ out) {
    __shared__ __align__(16) float sW[OB][IN_DIM * N_WIN];   // 32 KB
    __shared__ __align__(16) float sXa[IN_DIM][XDIM];
    __shared__ __align__(16) float sXb[IN_DIM][XDIM];

    const int tid    = threadIdx.x;
    const int warp   = tid >> 5;
    const int lane   = tid & 31;
    const int T0     = blockIdx.x * TT;
    const int o_base = blockIdx.y * OB;
    const int b      = blockIdx.z;

    // Load weights (contiguous [o][i*64+w] rows) — 2048 float4
    {
        const float4* wg = reinterpret_cast<const float4*>(weight) + (size_t)o_base * 128;
        float4* ws = reinterpret_cast<float4*>(sW);
#pragma unroll
        for (int r = 0; r < 16; ++r)
            ws[tid + r * 128] = wg[tid + r * 128];
    }
    // Load X tile: global index PAD + u, with u = T0 - 64 + j  →  g_X[b][i][T0 + j]
#pragma unroll
    for (int i = 0; i < IN_DIM; ++i) {
        const float* gx = &g_X[b][i][T0];
        for (int j = tid; j < XLEN; j += 128) {
            sXa[i][j] = gx[j];
            sXb[i][j] = gx[j + 1];   // tail pad in g_X makes this always in-bounds
        }
    }
    __syncthreads();

    const int tl0 = lane * 2;        // 0..62
    const int tl1 = tl0 + 64;        // 64..126

    unsigned long long acc[4][2];
#pragma unroll
    for (int oo = 0; oo < 4; ++oo) { acc[oo][0] = 0ull; acc[oo][1] = 0ull; }

    const float* wrow = &sW[warp * 4][0];

#define DW_STEP(DW, C0, C1, C2, C3)                                              \
    {                                                                            \
        const int w = w4 + (DW);                                                 \
        unsigned long long xv0, xv1;                                             \
        if ((DW) & 1) {                                                          \
            xv0 = lds2(xb + (tl0 + 63 - w));                                     \
            xv1 = lds2(xb + (tl1 + 63 - w));                                     \
        } else {                                                                 \
            xv0 = lds2(xa + (tl0 + 64 - w));                                     \
            xv1 = lds2(xa + (tl1 + 64 - w));                                     \
        }                                                                        \
        unsigned long long wv;                                                   \
        wv = pack2(C0); acc[0][0] = ffma2(wv, xv0, acc[0][0]);                   \
                        acc[0][1] = ffma2(wv, xv1, acc[0][1]);                   \
        wv = pack2(C1); acc[1][0] = ffma2(wv, xv0, acc[1][0]);                   \
                        acc[1][1] = ffma2(wv, xv1, acc[1][1]);                   \
        wv = pack2(C2); acc[2][0] = ffma2(wv, xv0, acc[2][0]);                   \
                        acc[2][1] = ffma2(wv, xv1, acc[2][1]);                   \
        wv = pack2(C3); acc[3][0] = ffma2(wv, xv0, acc[3][0]);                   \
                        acc[3][1] = ffma2(wv, xv1, acc[3][1]);                   \
    }

#pragma unroll 1
    for (int i = 0; i < IN_DIM; ++i) {
        const float* xa = &sXa[i][0];
        const float* xb = &sXb[i][0];
        const float* w0 = wrow + i * N_WIN;
#pragma unroll
        for (int w4 = 0; w4 < N_WIN; w4 += 4) {
            float4 q0 = *reinterpret_cast<const float4*>(w0 + w4);
            float4 q1 = *reinterpret_cast<const float4*>(w0 +  512 + w4);
            float4 q2 = *reinterpret_cast<const float4*>(w0 + 1024 + w4);
            float4 q3 = *reinterpret_cast<const float4*>(w0 + 1536 + w4);
            DW_STEP(0, q0.x, q1.x, q2.x, q3.x)
            DW_STEP(1, q0.y, q1.y, q2.y, q3.y)
            DW_STEP(2, q0.z, q1.z, q2.z, q3.z)
            DW_STEP(3, q0.w, q1.w, q2.w, q3.w)
        }
    }
#undef DW_STEP

    // Epilogue: add bias, store float2 pairs (coalesced across lanes)
#pragma unroll
    for (int oo = 0; oo < 4; ++oo) {
        const int o = o_base + warp * 4 + oo;
        const float bo = __ldg(&bias[o]);
        float2 r0 = unpack2(acc[oo][0]); r0.x += bo; r0.y += bo;
        float2 r1 = unpack2(acc[oo][1]); r1.x += bo; r1.y += bo;
        float* op = out + ((size_t)(b * OUT_D + o)) * N_REAL + T0;
        *reinterpret_cast<float2*>(op + tl0) = r0;
        *reinterpret_cast<float2*>(op + tl1) = r1;
    }
}

// ---------------- launch ----------------

extern "C" void kernel_launch(void* const* d_in, const int* in_sizes, int n_in,
                              void* d_out, int out_size) {
    (void)in_sizes; (void)n_in; (void)out_size;
    const float* x      = (const float*)d_in[0];   // (B, IN_DIM, N_SEQ)
    const float* weight = (const float*)d_in[1];   // (OUT_D, IN_DIM, N_WIN)
    const float* bias   = (const float*)d_in[2];   // (OUT_D)
    const int*   idx    = (const int*)  d_in[3];   // (B, N_SEQ)
    float* out = (float*)d_out;                    // (B, OUT_D, N_REAL)

    const int zTotal = NB * IN_DIM * ROW / 4;
    zero_kernel<<<(zTotal + 255) / 256, 256>>>();
    scatter_kernel<<<(NB * IN_DIM * N_SEQ) / 256, 256>>>(x, idx);

    dim3 grid(N_REAL / TT, OUT_D / OB, NB);        // (48, 4, 4)
    conv_kernel<<<grid, 128>>>(weight, bias, out);
}

// round 10
// speedup vs baseline: 1.0423x; 1.0423x over previous
#include <cuda_runtime.h>

#define NB     4
#define IN_DIM 8
#define OUT_D  64
#define N_WIN  64
#define N_SEQ  4096
#define N_REAL 6144
#define PAD    64
#define ROW    (PAD + N_REAL + 8)   // 6216 floats per (b,i) row
#define TT     256                  // t per block
#define OB     16                   // o per block
#define XLEN   (TT + N_WIN)         // 320
#define XDIM   320

__device__ __align__(16) float g_X[NB][IN_DIM][ROW];

// ---------------- fused zero + scatter: one block per (b,i) row ----------------

__global__ void scatter_kernel(const float* __restrict__ x, const int* __restrict__ idx) {
    const int b = blockIdx.x >> 3;
    const int i = blockIdx.x & 7;
    float* row = g_X[b][i];
    const int tid = threadIdx.x;

    const float4 z = make_float4(0.f, 0.f, 0.f, 0.f);
    for (int j = tid; j < ROW / 4; j += 512)
        reinterpret_cast<float4*>(row)[j] = z;
    __syncthreads();

    const int*   ib = idx + b * N_SEQ;
    const float* xb = x + (size_t)(b * IN_DIM + i) * N_SEQ;
    for (int s = tid; s < N_SEQ; s += 512)
        row[PAD + ib[s]] = xb[s];
}

// ---------------- f32x2 helpers ----------------

__device__ __forceinline__ unsigned long long ffma2(unsigned long long a,
                                                    unsigned long long b,
                                                    unsigned long long c) {
    unsigned long long d;
    asm("fma.rn.f32x2 %0, %1, %2, %3;" : "=l"(d) : "l"(a), "l"(b), "l"(c));
    return d;
}
__device__ __forceinline__ float2 unpack2(unsigned long long v) {
    float2 r;
    asm("mov.b64 {%0, %1}, %2;" : "=f"(r.x), "=f"(r.y) : "l"(v));
    return r;
}
__device__ __forceinline__ unsigned long long lds2(const float* p) {
    return *reinterpret_cast<const unsigned long long*>(p);
}

// ---------------- conv ----------------
// out[b,o,t] = bias[o] + sum_{i,w} W[o,i,w] * Xhat[b,i,t-w]
// Block: one b, 16 o-rows, 256 t. 4 warps split o (4 rows each); lane covers
// t-pairs {2L, 2L+1} + 3 more strided by 64. Weights pre-duplicated in shared
// as (w,w) float2 so the inner loop needs zero packing MOVs; one broadcast
// LDS.128 yields the f32x2 weight operands for two consecutive lags.

extern __shared__ float smem[];   // [sW2: 8192 float2][sXa: 8x320][sXb: 8x320]

__global__ __launch_bounds__(128, 2)
void conv_kernel(const float* __restrict__ weight,
                 const float* __restrict__ bias,
                 float* __restrict__ out) {
    float2* sW2 = reinterpret_cast<float2*>(smem);     // 8192 entries (64 KB)
    float*  sXa = smem + 16384;
    float*  sXb = sXa + IN_DIM * XDIM;

    const int tid    = threadIdx.x;
    const int warp   = tid >> 5;
    const int lane   = tid & 31;
    const int T0     = blockIdx.x * TT;
    const int o_base = blockIdx.y * OB;
    const int b      = blockIdx.z;

    // Load 16 weight rows (contiguous 512 floats each), duplicating to pairs.
    {
        const float4* wg = reinterpret_cast<const float4*>(weight + (size_t)o_base * 512);
#pragma unroll
        for (int r = 0; r < 16; ++r) {
            const int f4 = tid + r * 128;        // 0..2047
            float4 v = wg[f4];
            const int f = f4 * 4;
            sW2[f + 0] = make_float2(v.x, v.x);
            sW2[f + 1] = make_float2(v.y, v.y);
            sW2[f + 2] = make_float2(v.z, v.z);
            sW2[f + 3] = make_float2(v.w, v.w);
        }
    }
    // X tile: sXa[j] = Xhat[T0-64+j], sXb[j] = sXa[j+1] (odd-lag aligned pairs)
#pragma unroll
    for (int i = 0; i < IN_DIM; ++i) {
        const float* gx = &g_X[b][i][T0];
#pragma unroll
        for (int r = 0; r < 3; ++r) {
            const int j = tid + r * 128;
            if (j < XLEN) {
                sXa[i * XDIM + j] = gx[j];
                sXb[i * XDIM + j] = gx[j + 1];   // tail pad keeps this in-bounds
            }
        }
    }
    __syncthreads();

    const int tl = lane * 2;
    unsigned long long acc[4][4];
#pragma unroll
    for (int oo = 0; oo < 4; ++oo)
#pragma unroll
        for (int p = 0; p < 4; ++p) acc[oo][p] = 0ull;

    const float2* wbase = sW2 + (size_t)(warp * 4) * 512;

#pragma unroll 1
    for (int i = 0; i < IN_DIM; ++i) {
        const float*  xa = sXa + i * XDIM + tl + 64;   // even lag: [p*64 - w2]
        const float*  xb = sXb + i * XDIM + tl + 62;   // odd  lag: [p*64 - w2]
        const float2* wv = wbase + i * 64;
#pragma unroll
        for (int w2 = 0; w2 < N_WIN; w2 += 2) {
            unsigned long long wA[4], wB[4];
#pragma unroll
            for (int oo = 0; oo < 4; ++oo) {
                ulonglong2 q = *reinterpret_cast<const ulonglong2*>(&wv[oo * 512 + w2]);
                wA[oo] = q.x;   // lag w2   (duplicated pair)
                wB[oo] = q.y;   // lag w2+1 (duplicated pair)
            }
            unsigned long long xe[4], xo[4];
#pragma unroll
            for (int p = 0; p < 4; ++p) xe[p] = lds2(xa + p * 64 - w2);
#pragma unroll
            for (int p = 0; p < 4; ++p) xo[p] = lds2(xb + p * 64 - w2);
#pragma unroll
            for (int oo = 0; oo < 4; ++oo)
#pragma unroll
                for (int p = 0; p < 4; ++p)
                    acc[oo][p] = ffma2(wA[oo], xe[p], acc[oo][p]);
#pragma unroll
            for (int oo = 0; oo < 4; ++oo)
#pragma unroll
                for (int p = 0; p < 4; ++p)
                    acc[oo][p] = ffma2(wB[oo], xo[p], acc[oo][p]);
        }
    }

    // Epilogue: bias + coalesced float2 stores
#pragma unroll
    for (int oo = 0; oo < 4; ++oo) {
        const int o = o_base + warp * 4 + oo;
        const float bo = __ldg(&bias[o]);
        float* op = out + ((size_t)(b * OUT_D + o)) * N_REAL + T0 + tl;
#pragma unroll
        for (int p = 0; p < 4; ++p) {
            float2 r = unpack2(acc[oo][p]);
            r.x += bo; r.y += bo;
            reinterpret_cast<float2*>(op)[p * 32] = r;   // op + p*64 floats
        }
    }
}

// ---------------- launch ----------------

extern "C" void kernel_launch(void* const* d_in, const int* in_sizes, int n_in,
                              void* d_out, int out_size) {
    (void)in_sizes; (void)n_in; (void)out_size;
    const float* x      = (const float*)d_in[0];   // (B, IN_DIM, N_SEQ)
    const float* weight = (const float*)d_in[1];   // (OUT_D, IN_DIM, N_WIN)
    const float* bias   = (const float*)d_in[2];   // (OUT_D)
    const int*   idx    = (const int*)  d_in[3];   // (B, N_SEQ)
    float* out = (float*)d_out;                    // (B, OUT_D, N_REAL)

    const size_t shbytes = 8192 * sizeof(float2) + 2 * IN_DIM * XDIM * sizeof(float); // 86016
    cudaFuncSetAttribute(conv_kernel, cudaFuncAttributeMaxDynamicSharedMemorySize, (int)shbytes);

    scatter_kernel<<<NB * IN_DIM, 512>>>(x, idx);

    dim3 grid(N_REAL / TT, OUT_D / OB, NB);        // (24, 4, 4)
    conv_kernel<<<grid, 128, shbytes>>>(weight, bias, out);
}